// round 12
// baseline (speedup 1.0000x reference)
#include <cuda_runtime.h>
#include <cuda_bf16.h>

// Problem constants (fixed by the dataset): B=256, T=512, K=128
#define Bn 256
#define Tn 512
#define Kn 128

// Device scratch (no allocs allowed).
__device__ float g_partial[Bn];
__device__ int   g_perm[Bn];   // g_perm[rank] = batch index, by seq_len
__device__ int   g_done;       // zero-init; last CTA resets to 0 each run

// ---- scheduler: grid=32 x 256 threads; warp w ranks batch 8*bx+w ----------
__global__ void crf_sched_kernel(const int* __restrict__ seq_lens)
{
    const int lane = threadIdx.x & 31;
    const int i    = blockIdx.x * 8 + (threadIdx.x >> 5);
    const int Li   = seq_lens[i];
    int r = 0;
    #pragma unroll
    for (int kk = 0; kk < 8; kk++) {
        int k  = lane + 32 * kk;
        int Lk = seq_lens[k];
        r += (Lk < Li) || (Lk == Li && k < i);   // unique ranks
    }
    #pragma unroll
    for (int o = 16; o; o >>= 1) r += __shfl_xor_sync(0xffffffffu, r, o);
    if (lane == 0) g_perm[r] = i;
}

// Beta layout (bf16): half0 at elements [0,64), half1 at [72,136).
// Byte bases 0 / 144: LDS.128 line k of the two halves hits disjoint bank
// quads -> conflict-free 2-address broadcast. (144 % 16 == 0.)
#define HOFF 72
#define BSLOT(j) (((j) < 64) ? (j) : ((j) + 8))

// Split named barrier (producer/consumer pattern): each phase completes at
// 512 = 256 arrives + 256 syncs. arrive right after STS releases the thread
// to do independent work (LDG prefetch, exp precompute) DURING the wait.
#define GARR()  asm volatile("bar.arrive 1, 512;" ::: "memory")
#define GSYNC() asm volatile("bar.sync   1, 512;" ::: "memory")

__device__ __forceinline__ float frcp(float x) {
    float q; asm("rcp.approx.f32 %0, %1;" : "=f"(q) : "f"(x));
    return q;
}

// One scan step. Thread tau: column j=tau>>1, half h=tau&1 owns 64 i's as
// 32 bf16x2 weight regs. sync -> 8 LDS.128 + 32 HFMA2 + pure-bf16 tail ->
// STS -> arrive. cj comes in precomputed: non-renorm steps get a ready
// bf16x2 CE_; the renorm step multiplies fp32 E0_ by rcp(beta[0]) (same
// shift identity: S accumulates logf(r), beta gets 1/r -> exact LSE shift).
#define CRF_STEP_N(CE_) do {                                                 \
    GSYNC();                                                                 \
    const __nv_bfloat16* bp_ = sh_beta[cur];                                 \
    __nv_bfloat162 cj2_ = (CE_);                                             \
    const uint4* ap_ = (const uint4*)(bp_ + HOFF * h);                       \
    __nv_bfloat162 z_; z_.x = __float2bfloat16(0.f); z_.y = z_.x;            \
    __nv_bfloat162 a0_ = z_, a1_ = z_, a2_ = z_, a3_ = z_;                   \
    _Pragma("unroll")                                                        \
    for (int k_ = 0; k_ < 8; k_++) {                                         \
        uint4 v_ = ap_[k_];                 /* LDS.128: 8 betas (4 pairs) */ \
        a0_ = __hfma2(*(__nv_bfloat162*)&v_.x, eT2[4 * k_ + 0], a0_);        \
        a1_ = __hfma2(*(__nv_bfloat162*)&v_.y, eT2[4 * k_ + 1], a1_);        \
        a2_ = __hfma2(*(__nv_bfloat162*)&v_.z, eT2[4 * k_ + 2], a2_);        \
        a3_ = __hfma2(*(__nv_bfloat162*)&v_.w, eT2[4 * k_ + 3], a3_);        \
    }                                                                        \
    __nv_bfloat162 s_ = __hadd2(__hadd2(a0_, a1_), __hadd2(a2_, a3_));       \
    __nv_bfloat162 sw_ = __lowhigh2highlow(s_);                              \
    __nv_bfloat162 hs_ = __hadd2(s_, sw_);      /* both lanes = half-sum */  \
    unsigned hu_  = __shfl_xor_sync(0xffffffffu, *(unsigned*)&hs_, 1);       \
    __nv_bfloat162 tot_ = __hadd2(hs_, *(__nv_bfloat162*)&hu_);              \
    __nv_bfloat162 nb2_ = __hmul2(tot_, cj2_);                               \
    if (!h) sh_beta[cur ^ 1][slotj] = nb2_.x;                                \
    GARR();                                                                  \
    cur ^= 1;                                                                \
} while (0)

#define CRF_STEP_R(E0_) do {                                                 \
    GSYNC();                                                                 \
    const __nv_bfloat16* bp_ = sh_beta[cur];                                 \
    float rr_ = __bfloat162float(bp_[0]);                                    \
    S += __logf(rr_);                                                        \
    __nv_bfloat162 cj2_ = __float2bfloat162_rn((E0_) * frcp(rr_));           \
    const uint4* ap_ = (const uint4*)(bp_ + HOFF * h);                       \
    __nv_bfloat162 z_; z_.x = __float2bfloat16(0.f); z_.y = z_.x;            \
    __nv_bfloat162 a0_ = z_, a1_ = z_, a2_ = z_, a3_ = z_;                   \
    _Pragma("unroll")                                                        \
    for (int k_ = 0; k_ < 8; k_++) {                                         \
        uint4 v_ = ap_[k_];                                                  \
        a0_ = __hfma2(*(__nv_bfloat162*)&v_.x, eT2[4 * k_ + 0], a0_);        \
        a1_ = __hfma2(*(__nv_bfloat162*)&v_.y, eT2[4 * k_ + 1], a1_);        \
        a2_ = __hfma2(*(__nv_bfloat162*)&v_.z, eT2[4 * k_ + 2], a2_);        \
        a3_ = __hfma2(*(__nv_bfloat162*)&v_.w, eT2[4 * k_ + 3], a3_);        \
    }                                                                        \
    __nv_bfloat162 s_ = __hadd2(__hadd2(a0_, a1_), __hadd2(a2_, a3_));       \
    __nv_bfloat162 sw_ = __lowhigh2highlow(s_);                              \
    __nv_bfloat162 hs_ = __hadd2(s_, sw_);                                   \
    unsigned hu_  = __shfl_xor_sync(0xffffffffu, *(unsigned*)&hs_, 1);       \
    __nv_bfloat162 tot_ = __hadd2(hs_, *(__nv_bfloat162*)&hu_);              \
    __nv_bfloat162 nb2_ = __hmul2(tot_, cj2_);                               \
    if (!h) sh_beta[cur ^ 1][slotj] = nb2_.x;                                \
    GARR();                                                                  \
    cur ^= 1;                                                                \
} while (0)

// grid=128 CTAs, 256 threads, one CTA/SM. CTA c runs batches perm[c] then
// perm[255-c] sequentially (balanced pairs). Thread tau: column j=tau>>1,
// half h=tau&1 (proven layout). bf16 matvec + bf16 tail; fp32 elsewhere.
// Split barrier hides LDG prefetch + exp precompute inside the wait window.
__global__ __launch_bounds__(256, 1) void crf_forward_kernel(
    const float* __restrict__ logits,   // [B, T, K]
    const int*   __restrict__ labels,   // [B, T]
    const int*   __restrict__ seq_lens, // [B]
    const float* __restrict__ trans,    // [K, K] trans[i*K + j]
    float* __restrict__ out)
{
    __shared__ __align__(16) __nv_bfloat16 sh_beta[2][144];
    __shared__ float sh_wred[8];
    __shared__ int   sh_last;

    const int c    = blockIdx.x;          // 0..127
    const int tau  = threadIdx.x;         // 0..255
    const int j    = tau >> 1;            // column 0..127
    const int h    = tau & 1;             // half
    const int lane = tau & 31;
    const int warp = tau >> 5;
    const int slotj = BSLOT(j);

    const int bA = g_perm[c];
    const int bB = g_perm[Bn - 1 - c];

    // expT rows [64h, 64h+64) of column j, packed bf16x2 over row-pairs
    __nv_bfloat162 eT2[32];
    #pragma unroll
    for (int k = 0; k < 32; k++) {
        float e0 = __expf(trans[(64 * h + 2 * k)     * Kn + j]);
        float e1 = __expf(trans[(64 * h + 2 * k + 1) * Kn + j]);
        eT2[k] = __floats2bfloat162_rn(e0, e1);
    }

    for (int p = 0; p < 2; p++) {
        const int b = p ? bB : bA;
        const int    Tlen = seq_lens[b];                  // 1..512
        const float* lg   = logits + (size_t)b * Tn * Kn;
        const int*   lb   = labels + b * Tn;

        // ---------- gold-path score: unary + pairwise (fp32 exact) --------
        float sc = 0.f;
        for (int t = tau; t < Tlen; t += 256) {
            int y = lb[t];
            sc += lg[t * Kn + y];
            if (t >= 1) sc += trans[lb[t - 1] * Kn + y];
        }
        #pragma unroll
        for (int o = 16; o; o >>= 1) sc += __shfl_xor_sync(0xffffffffu, sc, o);
        if (lane == 0) sh_wred[warp] = sc;

        // beta_0 = exp(logits[b,0,:]) in bf16, S = 0
        if (!h) sh_beta[0][slotj] = __float2bfloat16(__expf(lg[j]));

        #define ROW(tt) lg[(((tt) < Tn) ? (tt) : (Tn - 1)) * Kn + j]
        // exp pipeline for rows t..t+3 of the current unroll iteration:
        //   Ef0 fp32 (renorm slot), ce1..ce3 bf16x2 (plain slots)
        // raw prefetch la0..la3 = rows t+4..t+7
        float Ef0 = __expf(ROW(1));
        __nv_bfloat162 ce1 = __float2bfloat162_rn(__expf(ROW(2)));
        __nv_bfloat162 ce2 = __float2bfloat162_rn(__expf(ROW(3)));
        __nv_bfloat162 ce3 = __float2bfloat162_rn(__expf(ROW(4)));
        float la0 = ROW(5), la1 = ROW(6), la2 = ROW(7), la3 = ROW(8);

        __syncthreads();                     // beta_0 + sh_wred visible
        float score = 0.f;
        #pragma unroll
        for (int w = 0; w < 8; w++) score += sh_wred[w];
        GARR();                              // prime barrier-1 phase

        // ---------- forward recursion, 4x unrolled, renorm 1-in-4 ---------
        // Indep work after each arrive: rotate the exp pipeline + prefetch.
        float S   = 0.f;
        int   cur = 0;
        int   t   = 1;
        while (t + 3 < Tlen) {
            float Ef0n; __nv_bfloat162 cen1, cen2, cen3;
            CRF_STEP_R(Ef0);
              Ef0n = __expf(la0);                       la0 = ROW(t + 8);
            CRF_STEP_N(ce1);
              cen1 = __float2bfloat162_rn(__expf(la1)); la1 = ROW(t + 9);
            CRF_STEP_N(ce2);
              cen2 = __float2bfloat162_rn(__expf(la2)); la2 = ROW(t + 10);
            CRF_STEP_N(ce3);
              cen3 = __float2bfloat162_rn(__expf(la3)); la3 = ROW(t + 11);
            Ef0 = Ef0n; ce1 = cen1; ce2 = cen2; ce3 = cen3;
            t += 4;
        }
        // remainder <= 3 steps; pipeline holds rows t..t+2 (Tlen uniform)
        if (t     < Tlen) CRF_STEP_R(Ef0);
        if (t + 1 < Tlen) CRF_STEP_N(ce1);
        if (t + 2 < Tlen) CRF_STEP_N(ce2);
        #undef ROW
        GSYNC();                             // consume final arrive; beta ok

        // ---------- log_z = S + log(sum_j beta_j) (fp32 reduce) -----------
        float v = (tau < Kn) ? __bfloat162float(sh_beta[cur][BSLOT(tau)]) : 0.f;
        #pragma unroll
        for (int o = 16; o; o >>= 1) v += __shfl_xor_sync(0xffffffffu, v, o);
        __syncthreads();                     // old sh_wred reads done
        if (lane == 0) sh_wred[warp] = v;
        __syncthreads();

        if (tau == 0) {
            float stot = ((sh_wred[0] + sh_wred[1]) + (sh_wred[2] + sh_wred[3]))
                       + ((sh_wred[4] + sh_wred[5]) + (sh_wred[6] + sh_wred[7]));
            g_partial[b] = S + __logf(stot) - score;   // per-batch NLL
        }
        __syncthreads();                     // smem safe for next batch
    }

    // ---------- fused final reduction: last CTA sums deterministically ----
    if (tau == 0) {
        __threadfence();
        int d = atomicAdd(&g_done, 1);
        sh_last = (d == (Bn / 2 - 1));
    }
    __syncthreads();
    if (sh_last) {
        __threadfence();                 // see all CTAs' g_partial writes
        float w = g_partial[tau];        // fixed-tree: deterministic
        #pragma unroll
        for (int o = 16; o; o >>= 1) w += __shfl_xor_sync(0xffffffffu, w, o);
        if (lane == 0) sh_wred[warp] = w;
        __syncthreads();
        if (tau == 0) {
            float s = ((sh_wred[0] + sh_wred[1]) + (sh_wred[2] + sh_wred[3]))
                    + ((sh_wred[4] + sh_wred[5]) + (sh_wred[6] + sh_wred[7]));
            out[0]  = s;
            g_done  = 0;                 // reset for next graph replay
        }
    }
}

extern "C" void kernel_launch(void* const* d_in, const int* in_sizes, int n_in,
                              void* d_out, int out_size)
{
    const float* logits   = (const float*)d_in[0];
    const int*   labels   = (const int*)  d_in[1];
    const int*   seq_lens = (const int*)  d_in[2];
    const float* trans    = (const float*)d_in[3];
    float*       out      = (float*)d_out;

    crf_sched_kernel<<<32, 256>>>(seq_lens);
    crf_forward_kernel<<<Bn / 2, 256>>>(logits, labels, seq_lens, trans, out);
}